// round 14
// baseline (speedup 1.0000x reference)
#include <cuda_runtime.h>
#include <math.h>

#define NN 100000
#define NE 1600000
#define ET (NE + NN)        // edges incl self loops = 1,700,000
#define FIN 136             // 128 + 8
#define D1 64               // heads1*hid1
#define COUT 40
#define SLOPE 0.2f

// ---------------- scratch (static device memory, no allocs) ----------------
__device__ float g_H1[NN * D1];
__device__ float g_as1[NN * 8];
__device__ float g_ad1[NN * 8];
__device__ float g_out1[NN * D1];
__device__ float g_H2[NN * COUT];
__device__ float g_as2[NN];
__device__ float g_ad2[NN];
__device__ int   g_deg[NN];      // zero-init at load; restored to 0 by k_scanA
__device__ int   g_off[NN + 1];
__device__ int   g_cursor[NN];
__device__ int   g_csrc[ET];
__device__ int   g_bsum[128];

static cudaStream_t s_csr = 0;
static cudaEvent_t  ev_fork = 0, ev_join = 0;
namespace {
struct _StreamInit {
    _StreamInit() {
        cudaStreamCreateWithFlags(&s_csr, cudaStreamNonBlocking);
        cudaEventCreateWithFlags(&ev_fork, cudaEventDisableTiming);
        cudaEventCreateWithFlags(&ev_join, cudaEventDisableTiming);
    }
};
_StreamInit _stream_init;
}

__device__ __forceinline__ float leaky(float x) { return x > 0.f ? x : SLOPE * x; }

// packed f32x2 helpers (sm_103a FFMA2 — PTX-only)
__device__ __forceinline__ unsigned long long bcast2(float v) {
    unsigned long long r;
    asm("mov.b64 %0, {%1, %1};" : "=l"(r) : "r"(__float_as_uint(v)));
    return r;
}
__device__ __forceinline__ void fma2(unsigned long long& acc, unsigned long long a,
                                     unsigned long long b) {
    asm("fma.rn.f32x2 %0, %1, %2, %3;" : "=l"(acc) : "l"(a), "l"(b), "l"(acc));
}
__device__ __forceinline__ void unpack2(unsigned long long p, float& lo, float& hi) {
    unsigned int l, h;
    asm("mov.b64 {%0, %1}, %2;" : "=r"(l), "=r"(h) : "l"(p));
    lo = __uint_as_float(l); hi = __uint_as_float(h);
}

// ---------------- CSR construction ----------------
__global__ void k_hist(const int* __restrict__ ei) {
    int t = blockIdx.x * blockDim.x + threadIdx.x;
    int base = t * 4;
    if (base < NE) {    // NE % 4 == 0 -> full quads only
        int4 d = *(const int4*)&ei[NE + base];
        atomicAdd(&g_deg[d.x], 1);
        atomicAdd(&g_deg[d.y], 1);
        atomicAdd(&g_deg[d.z], 1);
        atomicAdd(&g_deg[d.w], 1);
    }
}

__global__ void k_scanA() {   // warp-shuffle scan, 1024 threads/block
    __shared__ int wsum[32];
    int t = threadIdx.x;
    int i = blockIdx.x * 1024 + t;
    int v = 0;
    if (i < NN) {
        v = g_deg[i] + 1;    // +1 self loop
        g_deg[i] = 0;        // restore zero for next graph replay
    }
    int lane = t & 31, wid = t >> 5;
    int s = v;
    #pragma unroll
    for (int o = 1; o < 32; o <<= 1) {
        int u = __shfl_up_sync(0xffffffffu, s, o);
        if (lane >= o) s += u;
    }
    if (lane == 31) wsum[wid] = s;
    __syncthreads();
    if (wid == 0) {
        int ws = wsum[lane];
        #pragma unroll
        for (int o = 1; o < 32; o <<= 1) {
            int u = __shfl_up_sync(0xffffffffu, ws, o);
            if (lane >= o) ws += u;
        }
        wsum[lane] = ws;
    }
    __syncthreads();
    int base = wid ? wsum[wid - 1] : 0;
    int incl = base + s;
    if (i < NN) g_off[i] = incl - v;          // exclusive within block
    if (t == 1023) g_bsum[blockIdx.x] = incl; // inclusive block sum
}

__global__ void k_scanC(int nb) {
    __shared__ int sbase[2];
    int i = blockIdx.x * blockDim.x + threadIdx.x;
    int g0 = (blockIdx.x * 256) >> 10;
    if (threadIdx.x < 2) {
        int g = g0 + threadIdx.x;
        int s = 0;
        for (int b = 0; b < g && b < nb; ++b) s += g_bsum[b];
        sbase[threadIdx.x] = s;
    }
    __syncthreads();
    if (i < NN) {
        int o = g_off[i] + sbase[(i >> 10) - g0];
        g_off[i] = o;
        g_cursor[i] = o;
    }
    if (i == 0) g_off[NN] = ET;
}

__global__ void k_scatter(const int* __restrict__ ei) {
    int t = blockIdx.x * blockDim.x + threadIdx.x;
    int base = t * 4;
    if (base + 4 <= NE) {          // NE % 4 == 0: quads never straddle
        int4 s4 = *(const int4*)&ei[base];
        int4 d4 = *(const int4*)&ei[NE + base];
        g_csrc[atomicAdd(&g_cursor[d4.x], 1)] = s4.x;
        g_csrc[atomicAdd(&g_cursor[d4.y], 1)] = s4.y;
        g_csrc[atomicAdd(&g_cursor[d4.z], 1)] = s4.z;
        g_csrc[atomicAdd(&g_cursor[d4.w], 1)] = s4.w;
    } else {
        #pragma unroll
        for (int j = 0; j < 4; ++j) {
            int idx = base + j;
            if (idx >= NE && idx < ET) {
                int n = idx - NE;       // self loop
                g_csrc[atomicAdd(&g_cursor[n], 1)] = n;
            }
        }
    }
}

// ---------------- GEMM1: H1 = [x|topo] @ W1 (+ fused alpha1) ----------------
// 128 threads, tile 128x64, thread tile 8x8, double-buffered, FFMA2 inner loop.
__global__ void __launch_bounds__(128, 4)
k_gemm1(const float* __restrict__ x, const float* __restrict__ topo,
        const float* __restrict__ W1,
        const float* __restrict__ a_src, const float* __restrict__ a_dst) {
    __shared__ __align__(16) float Ws[FIN * D1];        // 34816 B
    __shared__ __align__(16) float xs[2][16][132];      // double buffer
    int tid = threadIdx.x;
    int tx = tid & 7, ty = tid >> 3;
    int nbase = blockIdx.x * 128;

    for (int i = tid; i < FIN * D1; i += 128) Ws[i] = W1[i];

    float4 pf[4];
    #pragma unroll
    for (int j = 0; j < 4; ++j) {
        int v = j * 128 + tid;
        int row = v >> 2, kq = v & 3;
        int n = nbase + row;
        pf[j] = make_float4(0.f, 0.f, 0.f, 0.f);
        if (n < NN) pf[j] = *(const float4*)&x[n * 128 + kq * 4];
    }
    #pragma unroll
    for (int j = 0; j < 4; ++j) {
        int v = j * 128 + tid;
        int row = v >> 2, kq = v & 3;
        xs[0][kq * 4 + 0][row] = pf[j].x;
        xs[0][kq * 4 + 1][row] = pf[j].y;
        xs[0][kq * 4 + 2][row] = pf[j].z;
        xs[0][kq * 4 + 3][row] = pf[j].w;
    }
    __syncthreads();

    unsigned long long acc2[8][4];
    #pragma unroll
    for (int r = 0; r < 8; ++r)
        #pragma unroll
        for (int c = 0; c < 4; ++c) acc2[r][c] = 0ULL;

    for (int c8 = 0; c8 < 8; ++c8) {
        if (c8 < 7) {
            #pragma unroll
            for (int j = 0; j < 4; ++j) {
                int v = j * 128 + tid;
                int row = v >> 2, kq = v & 3;
                int n = nbase + row;
                pf[j] = make_float4(0.f, 0.f, 0.f, 0.f);
                if (n < NN) pf[j] = *(const float4*)&x[n * 128 + (c8 + 1) * 16 + kq * 4];
            }
        } else {
            #pragma unroll
            for (int j = 0; j < 2; ++j) {
                int v = j * 128 + tid;
                int row = v >> 1, kq = v & 1;
                int n = nbase + row;
                pf[j] = make_float4(0.f, 0.f, 0.f, 0.f);
                if (n < NN) pf[j] = *(const float4*)&topo[n * 8 + kq * 4];
            }
        }
        int buf = c8 & 1;
        int k0 = c8 * 16;
        #pragma unroll
        for (int k = 0; k < 16; ++k) {
            float4 x0 = *(const float4*)&xs[buf][k][ty * 8];
            float4 x1 = *(const float4*)&xs[buf][k][ty * 8 + 4];
            const double2* wrp = (const double2*)&Ws[(k0 + k) * 64 + tx * 8];
            double2 wa = wrp[0], wb = wrp[1];
            unsigned long long wp[4] = {
                (unsigned long long)__double_as_longlong(wa.x),
                (unsigned long long)__double_as_longlong(wa.y),
                (unsigned long long)__double_as_longlong(wb.x),
                (unsigned long long)__double_as_longlong(wb.y)};
            float xv[8] = {x0.x, x0.y, x0.z, x0.w, x1.x, x1.y, x1.z, x1.w};
            #pragma unroll
            for (int r = 0; r < 8; ++r) {
                unsigned long long xrr = bcast2(xv[r]);
                fma2(acc2[r][0], xrr, wp[0]);
                fma2(acc2[r][1], xrr, wp[1]);
                fma2(acc2[r][2], xrr, wp[2]);
                fma2(acc2[r][3], xrr, wp[3]);
            }
        }
        __syncthreads();
        int nbuf = 1 - buf;
        if (c8 < 7) {
            #pragma unroll
            for (int j = 0; j < 4; ++j) {
                int v = j * 128 + tid;
                int row = v >> 2, kq = v & 3;
                xs[nbuf][kq * 4 + 0][row] = pf[j].x;
                xs[nbuf][kq * 4 + 1][row] = pf[j].y;
                xs[nbuf][kq * 4 + 2][row] = pf[j].z;
                xs[nbuf][kq * 4 + 3][row] = pf[j].w;
            }
        } else {
            #pragma unroll
            for (int j = 0; j < 2; ++j) {
                int v = j * 128 + tid;
                int row = v >> 1, kq = v & 1;
                xs[nbuf][kq * 4 + 0][row] = pf[j].x;
                xs[nbuf][kq * 4 + 1][row] = pf[j].y;
                xs[nbuf][kq * 4 + 2][row] = pf[j].z;
                xs[nbuf][kq * 4 + 3][row] = pf[j].w;
            }
        }
        __syncthreads();
    }

    #pragma unroll
    for (int k = 0; k < 8; ++k) {
        float4 x0 = *(const float4*)&xs[0][k][ty * 8];
        float4 x1 = *(const float4*)&xs[0][k][ty * 8 + 4];
        const double2* wrp = (const double2*)&Ws[(128 + k) * 64 + tx * 8];
        double2 wa = wrp[0], wb = wrp[1];
        unsigned long long wp[4] = {
            (unsigned long long)__double_as_longlong(wa.x),
            (unsigned long long)__double_as_longlong(wa.y),
            (unsigned long long)__double_as_longlong(wb.x),
            (unsigned long long)__double_as_longlong(wb.y)};
        float xv[8] = {x0.x, x0.y, x0.z, x0.w, x1.x, x1.y, x1.z, x1.w};
        #pragma unroll
        for (int r = 0; r < 8; ++r) {
            unsigned long long xrr = bcast2(xv[r]);
            fma2(acc2[r][0], xrr, wp[0]);
            fma2(acc2[r][1], xrr, wp[1]);
            fma2(acc2[r][2], xrr, wp[2]);
            fma2(acc2[r][3], xrr, wp[3]);
        }
    }

    float acc[8][8];
    #pragma unroll
    for (int r = 0; r < 8; ++r)
        #pragma unroll
        for (int c = 0; c < 4; ++c)
            unpack2(acc2[r][c], acc[r][2 * c], acc[r][2 * c + 1]);

    float as[8], ad[8];
    #pragma unroll
    for (int c = 0; c < 8; ++c) { as[c] = a_src[tx * 8 + c]; ad[c] = a_dst[tx * 8 + c]; }
    #pragma unroll
    for (int r = 0; r < 8; ++r) {
        int n = nbase + ty * 8 + r;
        if (n < NN) {
            *(float4*)&g_H1[n * 64 + tx * 8] =
                make_float4(acc[r][0], acc[r][1], acc[r][2], acc[r][3]);
            *(float4*)&g_H1[n * 64 + tx * 8 + 4] =
                make_float4(acc[r][4], acc[r][5], acc[r][6], acc[r][7]);
            float s = 0.f, d = 0.f;
            #pragma unroll
            for (int c = 0; c < 8; ++c) {
                s = fmaf(acc[r][c], as[c], s);
                d = fmaf(acc[r][c], ad[c], d);
            }
            g_as1[n * 8 + tx] = s;
            g_ad1[n * 8 + tx] = d;
        }
    }
}

// ------- layer1 aggregation: warp per dst, software-pipelined csrc --------
__global__ void k_agg1(const float* __restrict__ b1) {
    int w = (blockIdx.x * blockDim.x + threadIdx.x) >> 5;
    int lane = threadIdx.x & 31;
    if (w >= NN) return;
    int beg = g_off[w], end = g_off[w + 1];
    int c = 2 * lane, h = lane >> 2;
    float ad = __ldg(&g_ad1[w * 8 + h]);

    float z0 = 0.f, z1 = 0.f;
    float ax0 = 0.f, ay0 = 0.f, ax1 = 0.f, ay1 = 0.f;
    int i = beg;
    int s0 = 0, s1 = 0, s2 = 0, s3 = 0;
    if (i + 4 <= end) {
        s0 = __ldg(&g_csrc[i]);
        s1 = __ldg(&g_csrc[i + 1]);
        s2 = __ldg(&g_csrc[i + 2]);
        s3 = __ldg(&g_csrc[i + 3]);
    }
    while (i + 4 <= end) {
        int j = i + 4;
        int t0 = 0, t1 = 0, t2 = 0, t3 = 0;
        if (j + 4 <= end) {            // prefetch next quad of indices
            t0 = __ldg(&g_csrc[j]);
            t1 = __ldg(&g_csrc[j + 1]);
            t2 = __ldg(&g_csrc[j + 2]);
            t3 = __ldg(&g_csrc[j + 3]);
        }
        float e0 = leaky(__ldg(&g_as1[s0 * 8 + h]) + ad);
        float e1 = leaky(__ldg(&g_as1[s1 * 8 + h]) + ad);
        float e2 = leaky(__ldg(&g_as1[s2 * 8 + h]) + ad);
        float e3 = leaky(__ldg(&g_as1[s3 * 8 + h]) + ad);
        float2 v0 = __ldg((const float2*)&g_H1[s0 * 64 + c]);
        float2 v1 = __ldg((const float2*)&g_H1[s1 * 64 + c]);
        float2 v2 = __ldg((const float2*)&g_H1[s2 * 64 + c]);
        float2 v3 = __ldg((const float2*)&g_H1[s3 * 64 + c]);
        float x0 = __expf(e0), x1 = __expf(e1), x2 = __expf(e2), x3 = __expf(e3);
        z0 += x0 + x2; z1 += x1 + x3;
        ax0 = fmaf(x0, v0.x, ax0); ay0 = fmaf(x0, v0.y, ay0);
        ax1 = fmaf(x1, v1.x, ax1); ay1 = fmaf(x1, v1.y, ay1);
        ax0 = fmaf(x2, v2.x, ax0); ay0 = fmaf(x2, v2.y, ay0);
        ax1 = fmaf(x3, v3.x, ax1); ay1 = fmaf(x3, v3.y, ay1);
        i = j;
        s0 = t0; s1 = t1; s2 = t2; s3 = t3;
    }
    for (; i < end; ++i) {
        int s = __ldg(&g_csrc[i]);
        float x0 = __expf(leaky(__ldg(&g_as1[s * 8 + h]) + ad));
        float2 v0 = __ldg((const float2*)&g_H1[s * 64 + c]);
        z0 += x0;
        ax0 = fmaf(x0, v0.x, ax0); ay0 = fmaf(x0, v0.y, ay0);
    }
    float z = z0 + z1, ax = ax0 + ax1, ay = ay0 + ay1;
    float inv = 1.f / (z + 1e-16f);
    float ox = ax * inv + b1[c];
    float oy = ay * inv + b1[c + 1];
    ox = ox > 0.f ? ox : expm1f(ox);   // ELU
    oy = oy > 0.f ? oy : expm1f(oy);
    *(float2*)&g_out1[w * 64 + c] = make_float2(ox, oy);
}

// ---------------- GEMM2 (R6 form): H2 = out1 @ W2 (+ fused alpha2) --------
__global__ void k_gemm2(const float* __restrict__ W2,
                        const float* __restrict__ a_src, const float* __restrict__ a_dst) {
    __shared__ __align__(16) float Ws[64 * COUT];
    __shared__ __align__(16) float xs[16][132];
    int tid = threadIdx.x;
    int tx = tid & 7, ty = tid >> 3;
    int nbase = blockIdx.x * 128;

    for (int i = tid; i < 64 * COUT; i += 128) Ws[i] = W2[i];

    float acc[8][5];
    #pragma unroll
    for (int r = 0; r < 8; ++r)
        #pragma unroll
        for (int c = 0; c < 5; ++c) acc[r][c] = 0.f;

    for (int k0 = 0; k0 < 64; k0 += 16) {
        __syncthreads();
        #pragma unroll
        for (int j = 0; j < 4; ++j) {
            int v = j * 128 + tid;
            int row = v >> 2, kq = v & 3;
            int n = nbase + row;
            float4 val = make_float4(0.f, 0.f, 0.f, 0.f);
            if (n < NN) val = *(const float4*)&g_out1[n * 64 + k0 + kq * 4];
            xs[kq * 4 + 0][row] = val.x;
            xs[kq * 4 + 1][row] = val.y;
            xs[kq * 4 + 2][row] = val.z;
            xs[kq * 4 + 3][row] = val.w;
        }
        __syncthreads();
        #pragma unroll
        for (int k = 0; k < 16; ++k) {
            float4 x0 = *(const float4*)&xs[k][ty * 8];
            float4 x1 = *(const float4*)&xs[k][ty * 8 + 4];
            float xv[8] = {x0.x, x0.y, x0.z, x0.w, x1.x, x1.y, x1.z, x1.w};
            const float* wr = &Ws[(k0 + k) * COUT + tx * 5];
            float wv[5] = {wr[0], wr[1], wr[2], wr[3], wr[4]};
            #pragma unroll
            for (int r = 0; r < 8; ++r)
                #pragma unroll
                for (int c = 0; c < 5; ++c)
                    acc[r][c] = fmaf(xv[r], wv[c], acc[r][c]);
        }
    }

    float a2s[5], a2d[5];
    #pragma unroll
    for (int c = 0; c < 5; ++c) { a2s[c] = a_src[tx * 5 + c]; a2d[c] = a_dst[tx * 5 + c]; }
    #pragma unroll
    for (int r = 0; r < 8; ++r) {
        int n = nbase + ty * 8 + r;
        float s = 0.f, d = 0.f;
        #pragma unroll
        for (int c = 0; c < 5; ++c) {
            s = fmaf(acc[r][c], a2s[c], s);
            d = fmaf(acc[r][c], a2d[c], d);
        }
        #pragma unroll
        for (int o = 4; o; o >>= 1) {
            s += __shfl_xor_sync(0xffffffffu, s, o);
            d += __shfl_xor_sync(0xffffffffu, d, o);
        }
        if (n < NN) {
            #pragma unroll
            for (int c = 0; c < 5; ++c)
                g_H2[n * COUT + tx * 5 + c] = acc[r][c];
            if (tx == 0) { g_as2[n] = s; g_ad2[n] = d; }
        }
    }
}

// ---- layer2 aggregation + log_softmax: software-pipelined csrc -----------
__global__ void k_agg2(const float* __restrict__ b2, float* __restrict__ out) {
    int w = (blockIdx.x * blockDim.x + threadIdx.x) >> 5;
    int lane = threadIdx.x & 31;
    if (w >= NN) return;
    int beg = g_off[w], end = g_off[w + 1];
    float ad = __ldg(&g_ad2[w]);
    bool act = lane < 20;
    int c = 2 * lane;

    float z0 = 0.f, z1 = 0.f;
    float ax0 = 0.f, ay0 = 0.f, ax1 = 0.f, ay1 = 0.f;
    int i = beg;
    int s0 = 0, s1 = 0, s2 = 0, s3 = 0;
    if (i + 4 <= end) {
        s0 = __ldg(&g_csrc[i]);
        s1 = __ldg(&g_csrc[i + 1]);
        s2 = __ldg(&g_csrc[i + 2]);
        s3 = __ldg(&g_csrc[i + 3]);
    }
    while (i + 4 <= end) {
        int j = i + 4;
        int t0 = 0, t1 = 0, t2 = 0, t3 = 0;
        if (j + 4 <= end) {
            t0 = __ldg(&g_csrc[j]);
            t1 = __ldg(&g_csrc[j + 1]);
            t2 = __ldg(&g_csrc[j + 2]);
            t3 = __ldg(&g_csrc[j + 3]);
        }
        float x0 = __expf(leaky(__ldg(&g_as2[s0]) + ad));
        float x1 = __expf(leaky(__ldg(&g_as2[s1]) + ad));
        float x2 = __expf(leaky(__ldg(&g_as2[s2]) + ad));
        float x3 = __expf(leaky(__ldg(&g_as2[s3]) + ad));
        z0 += x0 + x2; z1 += x1 + x3;
        if (act) {
            float2 v0 = __ldg((const float2*)&g_H2[s0 * COUT + c]);
            float2 v1 = __ldg((const float2*)&g_H2[s1 * COUT + c]);
            float2 v2 = __ldg((const float2*)&g_H2[s2 * COUT + c]);
            float2 v3 = __ldg((const float2*)&g_H2[s3 * COUT + c]);
            ax0 = fmaf(x0, v0.x, ax0); ay0 = fmaf(x0, v0.y, ay0);
            ax1 = fmaf(x1, v1.x, ax1); ay1 = fmaf(x1, v1.y, ay1);
            ax0 = fmaf(x2, v2.x, ax0); ay0 = fmaf(x2, v2.y, ay0);
            ax1 = fmaf(x3, v3.x, ax1); ay1 = fmaf(x3, v3.y, ay1);
        }
        i = j;
        s0 = t0; s1 = t1; s2 = t2; s3 = t3;
    }
    for (; i < end; ++i) {
        int s = __ldg(&g_csrc[i]);
        float x0 = __expf(leaky(__ldg(&g_as2[s]) + ad));
        z0 += x0;
        if (act) {
            float2 v0 = __ldg((const float2*)&g_H2[s * COUT + c]);
            ax0 = fmaf(x0, v0.x, ax0); ay0 = fmaf(x0, v0.y, ay0);
        }
    }
    float z = z0 + z1, ax = ax0 + ax1, ay = ay0 + ay1;
    float inv = 1.f / (z + 1e-16f);
    float l0 = act ? (ax * inv + b2[c])     : -1e30f;
    float l1 = act ? (ay * inv + b2[c + 1]) : -1e30f;

    float lm = fmaxf(l0, l1);
    #pragma unroll
    for (int o = 16; o; o >>= 1) lm = fmaxf(lm, __shfl_xor_sync(0xffffffffu, lm, o));
    float es = act ? (__expf(l0 - lm) + __expf(l1 - lm)) : 0.f;
    #pragma unroll
    for (int o = 16; o; o >>= 1) es += __shfl_xor_sync(0xffffffffu, es, o);
    float lse = logf(es);
    if (act)
        *(float2*)&out[w * COUT + c] = make_float2(l0 - lm - lse, l1 - lm - lse);
}

// ---------------- launch ----------------
extern "C" void kernel_launch(void* const* d_in, const int* in_sizes, int n_in,
                              void* d_out, int out_size) {
    const float* x     = (const float*)d_in[0];
    const float* topo  = (const float*)d_in[1];
    const int*   ei    = (const int*)  d_in[2];
    const float* W1    = (const float*)d_in[3];
    const float* asrc1 = (const float*)d_in[4];
    const float* adst1 = (const float*)d_in[5];
    const float* b1    = (const float*)d_in[6];
    const float* W2    = (const float*)d_in[7];
    const float* asrc2 = (const float*)d_in[8];
    const float* adst2 = (const float*)d_in[9];
    const float* b2    = (const float*)d_in[10];
    float* out = (float*)d_out;
    (void)in_sizes; (void)n_in; (void)out_size;

    cudaEventRecord(ev_fork, 0);
    cudaStreamWaitEvent(s_csr, ev_fork, 0);

    int nb = (NN + 1023) / 1024;         // 98
    k_hist<<<(NE / 4 + 255) / 256, 256, 0, s_csr>>>(ei);           // launch 1
    k_scanA<<<nb, 1024, 0, s_csr>>>();                             // launch 2
    k_scanC<<<(NN + 255) / 256, 256, 0, s_csr>>>(nb);              // launch 3
    k_gemm1<<<(NN + 127) / 128, 128>>>(x, topo, W1, asrc1, adst1); // launch 4 (profiled)
    k_scatter<<<(ET / 4 + 255) / 256, 256, 0, s_csr>>>(ei);        // launch 5
    cudaEventRecord(ev_join, s_csr);

    cudaStreamWaitEvent(0, ev_join, 0);

    k_agg1<<<(NN + 7) / 8, 256>>>(b1);
    k_gemm2<<<(NN + 127) / 128, 128>>>(W2, asrc2, adst2);
    k_agg2<<<(NN + 7) / 8, 256>>>(b2, out);
}

// round 15
// speedup vs baseline: 1.1381x; 1.1381x over previous
#include <cuda_runtime.h>
#include <math.h>

#define NN 100000
#define NE 1600000
#define ET (NE + NN)        // edges incl self loops = 1,700,000
#define FIN 136             // 128 + 8
#define D1 64               // heads1*hid1
#define COUT 40
#define SLOPE 0.2f

// ---------------- scratch (static device memory, no allocs) ----------------
__device__ float g_H1[NN * D1];
__device__ float g_as1[NN * 8];
__device__ float g_ad1[NN * 8];
__device__ float g_out1[NN * D1];
__device__ float g_H2[NN * COUT];
__device__ float g_as2[NN];
__device__ float g_ad2[NN];
__device__ int   g_deg[NN];      // zero-init at load; restored to 0 by k_scanA
__device__ int   g_off[NN + 1];
__device__ int   g_cursor[NN];
__device__ int   g_csrc[ET];
__device__ int   g_bsum[128];

static cudaStream_t s_csr = 0;
static cudaEvent_t  ev_fork = 0, ev_join = 0;
namespace {
struct _StreamInit {
    _StreamInit() {
        cudaStreamCreateWithFlags(&s_csr, cudaStreamNonBlocking);
        cudaEventCreateWithFlags(&ev_fork, cudaEventDisableTiming);
        cudaEventCreateWithFlags(&ev_join, cudaEventDisableTiming);
    }
};
_StreamInit _stream_init;
}

__device__ __forceinline__ float leaky(float x) { return x > 0.f ? x : SLOPE * x; }

// packed f32x2 helpers (sm_103a FFMA2 — PTX-only)
__device__ __forceinline__ unsigned long long bcast2(float v) {
    unsigned long long r;
    asm("mov.b64 %0, {%1, %1};" : "=l"(r) : "r"(__float_as_uint(v)));
    return r;
}
__device__ __forceinline__ void fma2(unsigned long long& acc, unsigned long long a,
                                     unsigned long long b) {
    asm("fma.rn.f32x2 %0, %1, %2, %3;" : "=l"(acc) : "l"(a), "l"(b), "l"(acc));
}
__device__ __forceinline__ void unpack2(unsigned long long p, float& lo, float& hi) {
    unsigned int l, h;
    asm("mov.b64 {%0, %1}, %2;" : "=r"(l), "=r"(h) : "l"(p));
    lo = __uint_as_float(l); hi = __uint_as_float(h);
}

// ---------------- CSR construction ----------------
__global__ void k_hist(const int* __restrict__ ei) {
    int t = blockIdx.x * blockDim.x + threadIdx.x;
    int base = t * 4;
    if (base < NE) {    // NE % 4 == 0 -> full quads only
        int4 d = *(const int4*)&ei[NE + base];
        atomicAdd(&g_deg[d.x], 1);
        atomicAdd(&g_deg[d.y], 1);
        atomicAdd(&g_deg[d.z], 1);
        atomicAdd(&g_deg[d.w], 1);
    }
}

__global__ void k_scanA() {   // warp-shuffle scan, 1024 threads/block
    __shared__ int wsum[32];
    int t = threadIdx.x;
    int i = blockIdx.x * 1024 + t;
    int v = 0;
    if (i < NN) {
        v = g_deg[i] + 1;    // +1 self loop
        g_deg[i] = 0;        // restore zero for next graph replay
    }
    int lane = t & 31, wid = t >> 5;
    int s = v;
    #pragma unroll
    for (int o = 1; o < 32; o <<= 1) {
        int u = __shfl_up_sync(0xffffffffu, s, o);
        if (lane >= o) s += u;
    }
    if (lane == 31) wsum[wid] = s;
    __syncthreads();
    if (wid == 0) {
        int ws = wsum[lane];
        #pragma unroll
        for (int o = 1; o < 32; o <<= 1) {
            int u = __shfl_up_sync(0xffffffffu, ws, o);
            if (lane >= o) ws += u;
        }
        wsum[lane] = ws;
    }
    __syncthreads();
    int base = wid ? wsum[wid - 1] : 0;
    int incl = base + s;
    if (i < NN) g_off[i] = incl - v;          // exclusive within block
    if (t == 1023) g_bsum[blockIdx.x] = incl; // inclusive block sum
}

__global__ void k_scanC(int nb) {
    __shared__ int sbase[2];
    int i = blockIdx.x * blockDim.x + threadIdx.x;
    int g0 = (blockIdx.x * 256) >> 10;
    if (threadIdx.x < 2) {
        int g = g0 + threadIdx.x;
        int s = 0;
        for (int b = 0; b < g && b < nb; ++b) s += g_bsum[b];
        sbase[threadIdx.x] = s;
    }
    __syncthreads();
    if (i < NN) {
        int o = g_off[i] + sbase[(i >> 10) - g0];
        g_off[i] = o;
        g_cursor[i] = o;
    }
    if (i == 0) g_off[NN] = ET;
}

__global__ void k_scatter(const int* __restrict__ ei) {
    int t = blockIdx.x * blockDim.x + threadIdx.x;
    int base = t * 4;
    if (base + 4 <= NE) {          // NE % 4 == 0: quads never straddle
        int4 s4 = *(const int4*)&ei[base];
        int4 d4 = *(const int4*)&ei[NE + base];
        g_csrc[atomicAdd(&g_cursor[d4.x], 1)] = s4.x;
        g_csrc[atomicAdd(&g_cursor[d4.y], 1)] = s4.y;
        g_csrc[atomicAdd(&g_cursor[d4.z], 1)] = s4.z;
        g_csrc[atomicAdd(&g_cursor[d4.w], 1)] = s4.w;
    } else {
        #pragma unroll
        for (int j = 0; j < 4; ++j) {
            int idx = base + j;
            if (idx >= NE && idx < ET) {
                int n = idx - NE;       // self loop
                g_csrc[atomicAdd(&g_cursor[n], 1)] = n;
            }
        }
    }
}

// ---------------- GEMM1: H1 = [x|topo] @ W1 (+ fused alpha1) ----------------
// 128 threads, tile 128x64, thread tile 8x8, double-buffered, FFMA2 inner loop.
__global__ void __launch_bounds__(128, 4)
k_gemm1(const float* __restrict__ x, const float* __restrict__ topo,
        const float* __restrict__ W1,
        const float* __restrict__ a_src, const float* __restrict__ a_dst) {
    __shared__ __align__(16) float Ws[FIN * D1];        // 34816 B
    __shared__ __align__(16) float xs[2][16][132];      // double buffer
    int tid = threadIdx.x;
    int tx = tid & 7, ty = tid >> 3;
    int nbase = blockIdx.x * 128;

    for (int i = tid; i < FIN * D1; i += 128) Ws[i] = W1[i];

    float4 pf[4];
    #pragma unroll
    for (int j = 0; j < 4; ++j) {
        int v = j * 128 + tid;
        int row = v >> 2, kq = v & 3;
        int n = nbase + row;
        pf[j] = make_float4(0.f, 0.f, 0.f, 0.f);
        if (n < NN) pf[j] = *(const float4*)&x[n * 128 + kq * 4];
    }
    #pragma unroll
    for (int j = 0; j < 4; ++j) {
        int v = j * 128 + tid;
        int row = v >> 2, kq = v & 3;
        xs[0][kq * 4 + 0][row] = pf[j].x;
        xs[0][kq * 4 + 1][row] = pf[j].y;
        xs[0][kq * 4 + 2][row] = pf[j].z;
        xs[0][kq * 4 + 3][row] = pf[j].w;
    }
    __syncthreads();

    unsigned long long acc2[8][4];
    #pragma unroll
    for (int r = 0; r < 8; ++r)
        #pragma unroll
        for (int c = 0; c < 4; ++c) acc2[r][c] = 0ULL;

    for (int c8 = 0; c8 < 8; ++c8) {
        if (c8 < 7) {
            #pragma unroll
            for (int j = 0; j < 4; ++j) {
                int v = j * 128 + tid;
                int row = v >> 2, kq = v & 3;
                int n = nbase + row;
                pf[j] = make_float4(0.f, 0.f, 0.f, 0.f);
                if (n < NN) pf[j] = *(const float4*)&x[n * 128 + (c8 + 1) * 16 + kq * 4];
            }
        } else {
            #pragma unroll
            for (int j = 0; j < 2; ++j) {
                int v = j * 128 + tid;
                int row = v >> 1, kq = v & 1;
                int n = nbase + row;
                pf[j] = make_float4(0.f, 0.f, 0.f, 0.f);
                if (n < NN) pf[j] = *(const float4*)&topo[n * 8 + kq * 4];
            }
        }
        int buf = c8 & 1;
        int k0 = c8 * 16;
        #pragma unroll
        for (int k = 0; k < 16; ++k) {
            float4 x0 = *(const float4*)&xs[buf][k][ty * 8];
            float4 x1 = *(const float4*)&xs[buf][k][ty * 8 + 4];
            const double2* wrp = (const double2*)&Ws[(k0 + k) * 64 + tx * 8];
            double2 wa = wrp[0], wb = wrp[1];
            unsigned long long wp[4] = {
                (unsigned long long)__double_as_longlong(wa.x),
                (unsigned long long)__double_as_longlong(wa.y),
                (unsigned long long)__double_as_longlong(wb.x),
                (unsigned long long)__double_as_longlong(wb.y)};
            float xv[8] = {x0.x, x0.y, x0.z, x0.w, x1.x, x1.y, x1.z, x1.w};
            #pragma unroll
            for (int r = 0; r < 8; ++r) {
                unsigned long long xrr = bcast2(xv[r]);
                fma2(acc2[r][0], xrr, wp[0]);
                fma2(acc2[r][1], xrr, wp[1]);
                fma2(acc2[r][2], xrr, wp[2]);
                fma2(acc2[r][3], xrr, wp[3]);
            }
        }
        __syncthreads();
        int nbuf = 1 - buf;
        if (c8 < 7) {
            #pragma unroll
            for (int j = 0; j < 4; ++j) {
                int v = j * 128 + tid;
                int row = v >> 2, kq = v & 3;
                xs[nbuf][kq * 4 + 0][row] = pf[j].x;
                xs[nbuf][kq * 4 + 1][row] = pf[j].y;
                xs[nbuf][kq * 4 + 2][row] = pf[j].z;
                xs[nbuf][kq * 4 + 3][row] = pf[j].w;
            }
        } else {
            #pragma unroll
            for (int j = 0; j < 2; ++j) {
                int v = j * 128 + tid;
                int row = v >> 1, kq = v & 1;
                xs[nbuf][kq * 4 + 0][row] = pf[j].x;
                xs[nbuf][kq * 4 + 1][row] = pf[j].y;
                xs[nbuf][kq * 4 + 2][row] = pf[j].z;
                xs[nbuf][kq * 4 + 3][row] = pf[j].w;
            }
        }
        __syncthreads();
    }

    #pragma unroll
    for (int k = 0; k < 8; ++k) {
        float4 x0 = *(const float4*)&xs[0][k][ty * 8];
        float4 x1 = *(const float4*)&xs[0][k][ty * 8 + 4];
        const double2* wrp = (const double2*)&Ws[(128 + k) * 64 + tx * 8];
        double2 wa = wrp[0], wb = wrp[1];
        unsigned long long wp[4] = {
            (unsigned long long)__double_as_longlong(wa.x),
            (unsigned long long)__double_as_longlong(wa.y),
            (unsigned long long)__double_as_longlong(wb.x),
            (unsigned long long)__double_as_longlong(wb.y)};
        float xv[8] = {x0.x, x0.y, x0.z, x0.w, x1.x, x1.y, x1.z, x1.w};
        #pragma unroll
        for (int r = 0; r < 8; ++r) {
            unsigned long long xrr = bcast2(xv[r]);
            fma2(acc2[r][0], xrr, wp[0]);
            fma2(acc2[r][1], xrr, wp[1]);
            fma2(acc2[r][2], xrr, wp[2]);
            fma2(acc2[r][3], xrr, wp[3]);
        }
    }

    float acc[8][8];
    #pragma unroll
    for (int r = 0; r < 8; ++r)
        #pragma unroll
        for (int c = 0; c < 4; ++c)
            unpack2(acc2[r][c], acc[r][2 * c], acc[r][2 * c + 1]);

    float as[8], ad[8];
    #pragma unroll
    for (int c = 0; c < 8; ++c) { as[c] = a_src[tx * 8 + c]; ad[c] = a_dst[tx * 8 + c]; }
    #pragma unroll
    for (int r = 0; r < 8; ++r) {
        int n = nbase + ty * 8 + r;
        if (n < NN) {
            *(float4*)&g_H1[n * 64 + tx * 8] =
                make_float4(acc[r][0], acc[r][1], acc[r][2], acc[r][3]);
            *(float4*)&g_H1[n * 64 + tx * 8 + 4] =
                make_float4(acc[r][4], acc[r][5], acc[r][6], acc[r][7]);
            float s = 0.f, d = 0.f;
            #pragma unroll
            for (int c = 0; c < 8; ++c) {
                s = fmaf(acc[r][c], as[c], s);
                d = fmaf(acc[r][c], ad[c], d);
            }
            g_as1[n * 8 + tx] = s;
            g_ad1[n * 8 + tx] = d;
        }
    }
}

// ------- layer1 aggregation: 2 edges per warp-instruction -----------------
// lane = grp*16 + l; grp in {0,1} owns edge (pair base + grp);
// lane covers channels 4l..4l+3 (float4), head h = l>>1.
__global__ void k_agg1(const float* __restrict__ b1) {
    int w = (blockIdx.x * blockDim.x + threadIdx.x) >> 5;
    int lane = threadIdx.x & 31;
    if (w >= NN) return;
    int beg = g_off[w], end = g_off[w + 1];
    int l = lane & 15, grp = lane >> 4;
    int c = 4 * l, h = l >> 1;
    float ad = __ldg(&g_ad1[w * 8 + h]);

    float4 a = make_float4(0.f, 0.f, 0.f, 0.f);
    float z = 0.f;
    int i = beg;
    // 2 pairs (4 edges) per iteration
    for (; i + 4 <= end; i += 4) {
        int sA = __ldg(&g_csrc[i + grp]);
        int sB = __ldg(&g_csrc[i + 2 + grp]);
        float eA = leaky(__ldg(&g_as1[sA * 8 + h]) + ad);
        float eB = leaky(__ldg(&g_as1[sB * 8 + h]) + ad);
        float4 vA = __ldg((const float4*)&g_H1[sA * 64 + c]);
        float4 vB = __ldg((const float4*)&g_H1[sB * 64 + c]);
        float xA = __expf(eA), xB = __expf(eB);
        z += xA + xB;
        a.x = fmaf(xA, vA.x, a.x); a.y = fmaf(xA, vA.y, a.y);
        a.z = fmaf(xA, vA.z, a.z); a.w = fmaf(xA, vA.w, a.w);
        a.x = fmaf(xB, vB.x, a.x); a.y = fmaf(xB, vB.y, a.y);
        a.z = fmaf(xB, vB.z, a.z); a.w = fmaf(xB, vB.w, a.w);
    }
    // 1 pair (2 edges)
    for (; i + 2 <= end; i += 2) {
        int s = __ldg(&g_csrc[i + grp]);
        float e = leaky(__ldg(&g_as1[s * 8 + h]) + ad);
        float4 v = __ldg((const float4*)&g_H1[s * 64 + c]);
        float x = __expf(e);
        z += x;
        a.x = fmaf(x, v.x, a.x); a.y = fmaf(x, v.y, a.y);
        a.z = fmaf(x, v.z, a.z); a.w = fmaf(x, v.w, a.w);
    }
    // single tail edge: group 0 only (x forced 0 on group 1)
    if (i < end) {
        int s = __ldg(&g_csrc[i]);
        float e = leaky(__ldg(&g_as1[s * 8 + h]) + ad);
        float4 v = __ldg((const float4*)&g_H1[s * 64 + c]);
        float x = (grp == 0) ? __expf(e) : 0.f;
        z += x;
        a.x = fmaf(x, v.x, a.x); a.y = fmaf(x, v.y, a.y);
        a.z = fmaf(x, v.z, a.z); a.w = fmaf(x, v.w, a.w);
    }
    // combine the two edge-groups
    a.x += __shfl_xor_sync(0xffffffffu, a.x, 16);
    a.y += __shfl_xor_sync(0xffffffffu, a.y, 16);
    a.z += __shfl_xor_sync(0xffffffffu, a.z, 16);
    a.w += __shfl_xor_sync(0xffffffffu, a.w, 16);
    z   += __shfl_xor_sync(0xffffffffu, z, 16);
    if (grp == 0) {
        float inv = 1.f / (z + 1e-16f);
        float o0 = a.x * inv + b1[c];
        float o1 = a.y * inv + b1[c + 1];
        float o2 = a.z * inv + b1[c + 2];
        float o3 = a.w * inv + b1[c + 3];
        o0 = o0 > 0.f ? o0 : expm1f(o0);
        o1 = o1 > 0.f ? o1 : expm1f(o1);
        o2 = o2 > 0.f ? o2 : expm1f(o2);
        o3 = o3 > 0.f ? o3 : expm1f(o3);
        *(float4*)&g_out1[w * 64 + c] = make_float4(o0, o1, o2, o3);
    }
}

// ---------------- GEMM2 (R6 form): H2 = out1 @ W2 (+ fused alpha2) --------
__global__ void k_gemm2(const float* __restrict__ W2,
                        const float* __restrict__ a_src, const float* __restrict__ a_dst) {
    __shared__ __align__(16) float Ws[64 * COUT];
    __shared__ __align__(16) float xs[16][132];
    int tid = threadIdx.x;
    int tx = tid & 7, ty = tid >> 3;
    int nbase = blockIdx.x * 128;

    for (int i = tid; i < 64 * COUT; i += 128) Ws[i] = W2[i];

    float acc[8][5];
    #pragma unroll
    for (int r = 0; r < 8; ++r)
        #pragma unroll
        for (int c = 0; c < 5; ++c) acc[r][c] = 0.f;

    for (int k0 = 0; k0 < 64; k0 += 16) {
        __syncthreads();
        #pragma unroll
        for (int j = 0; j < 4; ++j) {
            int v = j * 128 + tid;
            int row = v >> 2, kq = v & 3;
            int n = nbase + row;
            float4 val = make_float4(0.f, 0.f, 0.f, 0.f);
            if (n < NN) val = *(const float4*)&g_out1[n * 64 + k0 + kq * 4];
            xs[kq * 4 + 0][row] = val.x;
            xs[kq * 4 + 1][row] = val.y;
            xs[kq * 4 + 2][row] = val.z;
            xs[kq * 4 + 3][row] = val.w;
        }
        __syncthreads();
        #pragma unroll
        for (int k = 0; k < 16; ++k) {
            float4 x0 = *(const float4*)&xs[k][ty * 8];
            float4 x1 = *(const float4*)&xs[k][ty * 8 + 4];
            float xv[8] = {x0.x, x0.y, x0.z, x0.w, x1.x, x1.y, x1.z, x1.w};
            const float* wr = &Ws[(k0 + k) * COUT + tx * 5];
            float wv[5] = {wr[0], wr[1], wr[2], wr[3], wr[4]};
            #pragma unroll
            for (int r = 0; r < 8; ++r)
                #pragma unroll
                for (int c = 0; c < 5; ++c)
                    acc[r][c] = fmaf(xv[r], wv[c], acc[r][c]);
        }
    }

    float a2s[5], a2d[5];
    #pragma unroll
    for (int c = 0; c < 5; ++c) { a2s[c] = a_src[tx * 5 + c]; a2d[c] = a_dst[tx * 5 + c]; }
    #pragma unroll
    for (int r = 0; r < 8; ++r) {
        int n = nbase + ty * 8 + r;
        float s = 0.f, d = 0.f;
        #pragma unroll
        for (int c = 0; c < 5; ++c) {
            s = fmaf(acc[r][c], a2s[c], s);
            d = fmaf(acc[r][c], a2d[c], d);
        }
        #pragma unroll
        for (int o = 4; o; o >>= 1) {
            s += __shfl_xor_sync(0xffffffffu, s, o);
            d += __shfl_xor_sync(0xffffffffu, d, o);
        }
        if (n < NN) {
            #pragma unroll
            for (int c = 0; c < 5; ++c)
                g_H2[n * COUT + tx * 5 + c] = acc[r][c];
            if (tx == 0) { g_as2[n] = s; g_ad2[n] = d; }
        }
    }
}

// ------- layer2 aggregation + log_softmax: 2 edges per warp-instruction ---
// lanes l<10 cover channels 4l..4l+3 (float4); grp owns edge (pair + grp).
__global__ void k_agg2(const float* __restrict__ b2, float* __restrict__ out) {
    int w = (blockIdx.x * blockDim.x + threadIdx.x) >> 5;
    int lane = threadIdx.x & 31;
    if (w >= NN) return;
    int beg = g_off[w], end = g_off[w + 1];
    float ad = __ldg(&g_ad2[w]);
    int l = lane & 15, grp = lane >> 4;
    bool act = l < 10;
    int c = 4 * l;          // 0..36 for act lanes

    float4 a = make_float4(0.f, 0.f, 0.f, 0.f);
    float z = 0.f;
    int i = beg;
    for (; i + 4 <= end; i += 4) {
        int sA = __ldg(&g_csrc[i + grp]);
        int sB = __ldg(&g_csrc[i + 2 + grp]);
        float xA = __expf(leaky(__ldg(&g_as2[sA]) + ad));
        float xB = __expf(leaky(__ldg(&g_as2[sB]) + ad));
        z += xA + xB;
        if (act) {
            float4 vA = __ldg((const float4*)&g_H2[sA * COUT + c]);
            float4 vB = __ldg((const float4*)&g_H2[sB * COUT + c]);
            a.x = fmaf(xA, vA.x, a.x); a.y = fmaf(xA, vA.y, a.y);
            a.z = fmaf(xA, vA.z, a.z); a.w = fmaf(xA, vA.w, a.w);
            a.x = fmaf(xB, vB.x, a.x); a.y = fmaf(xB, vB.y, a.y);
            a.z = fmaf(xB, vB.z, a.z); a.w = fmaf(xB, vB.w, a.w);
        }
    }
    for (; i + 2 <= end; i += 2) {
        int s = __ldg(&g_csrc[i + grp]);
        float x = __expf(leaky(__ldg(&g_as2[s]) + ad));
        z += x;
        if (act) {
            float4 v = __ldg((const float4*)&g_H2[s * COUT + c]);
            a.x = fmaf(x, v.x, a.x); a.y = fmaf(x, v.y, a.y);
            a.z = fmaf(x, v.z, a.z); a.w = fmaf(x, v.w, a.w);
        }
    }
    if (i < end) {
        int s = __ldg(&g_csrc[i]);
        float x = (grp == 0) ? __expf(leaky(__ldg(&g_as2[s]) + ad)) : 0.f;
        z += x;
        if (act) {
            float4 v = __ldg((const float4*)&g_H2[s * COUT + c]);
            a.x = fmaf(x, v.x, a.x); a.y = fmaf(x, v.y, a.y);
            a.z = fmaf(x, v.z, a.z); a.w = fmaf(x, v.w, a.w);
        }
    }
    // combine edge-groups
    a.x += __shfl_xor_sync(0xffffffffu, a.x, 16);
    a.y += __shfl_xor_sync(0xffffffffu, a.y, 16);
    a.z += __shfl_xor_sync(0xffffffffu, a.z, 16);
    a.w += __shfl_xor_sync(0xffffffffu, a.w, 16);
    z   += __shfl_xor_sync(0xffffffffu, z, 16);

    bool ow = act && (grp == 0);
    float inv = 1.f / (z + 1e-16f);
    float l0 = ow ? (a.x * inv + b2[c])     : -1e30f;
    float l1 = ow ? (a.y * inv + b2[c + 1]) : -1e30f;
    float l2 = ow ? (a.z * inv + b2[c + 2]) : -1e30f;
    float l3 = ow ? (a.w * inv + b2[c + 3]) : -1e30f;

    // log_softmax over 40 logits (10 lanes x 4)
    float lm = fmaxf(fmaxf(l0, l1), fmaxf(l2, l3));
    #pragma unroll
    for (int o = 16; o; o >>= 1) lm = fmaxf(lm, __shfl_xor_sync(0xffffffffu, lm, o));
    float es = ow ? (__expf(l0 - lm) + __expf(l1 - lm) + __expf(l2 - lm) + __expf(l3 - lm)) : 0.f;
    #pragma unroll
    for (int o = 16; o; o >>= 1) es += __shfl_xor_sync(0xffffffffu, es, o);
    float lse = logf(es);
    if (ow)
        *(float4*)&out[w * COUT + c] =
            make_float4(l0 - lm - lse, l1 - lm - lse, l2 - lm - lse, l3 - lm - lse);
}

// ---------------- launch ----------------
extern "C" void kernel_launch(void* const* d_in, const int* in_sizes, int n_in,
                              void* d_out, int out_size) {
    const float* x     = (const float*)d_in[0];
    const float* topo  = (const float*)d_in[1];
    const int*   ei    = (const int*)  d_in[2];
    const float* W1    = (const float*)d_in[3];
    const float* asrc1 = (const float*)d_in[4];
    const float* adst1 = (const float*)d_in[5];
    const float* b1    = (const float*)d_in[6];
    const float* W2    = (const float*)d_in[7];
    const float* asrc2 = (const float*)d_in[8];
    const float* adst2 = (const float*)d_in[9];
    const float* b2    = (const float*)d_in[10];
    float* out = (float*)d_out;
    (void)in_sizes; (void)n_in; (void)out_size;

    cudaEventRecord(ev_fork, 0);
    cudaStreamWaitEvent(s_csr, ev_fork, 0);

    int nb = (NN + 1023) / 1024;         // 98
    k_hist<<<(NE / 4 + 255) / 256, 256, 0, s_csr>>>(ei);           // launch 1
    k_scanA<<<nb, 1024, 0, s_csr>>>();                             // launch 2
    k_scanC<<<(NN + 255) / 256, 256, 0, s_csr>>>(nb);              // launch 3
    k_gemm1<<<(NN + 127) / 128, 128>>>(x, topo, W1, asrc1, adst1); // launch 4 (profiled)
    k_scatter<<<(ET / 4 + 255) / 256, 256, 0, s_csr>>>(ei);        // launch 5
    cudaEventRecord(ev_join, s_csr);

    cudaStreamWaitEvent(0, ev_join, 0);

    k_agg1<<<(NN + 7) / 8, 256>>>(b1);
    k_gemm2<<<(NN + 127) / 128, 128>>>(W2, asrc2, adst2);
    k_agg2<<<(NN + 7) / 8, 256>>>(b2, out);
}